// round 11
// baseline (speedup 1.0000x reference)
#include <cuda_runtime.h>
#include <math.h>

#define B_DIM 256
#define V_DIM 50257
#define SEGS  4
#define SEG_LEN 12565                 // ceil(V/4)
#define N_BIN 64                      // rows handled by self-normalizing bin CTAs
#define BIN_SMEM (V_DIM * 4)          // 201,028 B bin table
#define ZERO_START4 ((N_BIN * V_DIM) / 4)            // exact (64*V/4)
#define N4_AVG      ((B_DIM * V_DIM) / 4)            // 3,216,448

// Partial sum-of-exp per row segment: [b*SEGS + seg] (used by tile kernel only)
__device__ float g_partial[SEGS * B_DIM];

// ---------------------------------------------------------------------------
// Kernel 1: stats for ALL rows (tile transpose needs them) + zero rows >= N_BIN.
// ---------------------------------------------------------------------------
__global__ __launch_bounds__(256)
void stats_and_zero(const float* __restrict__ w, float4* __restrict__ avg4) {
    const int bid = blockIdx.x;
    const int b   = bid >> 2;
    const int seg = bid & 3;
    const int vs  = seg * SEG_LEN;
    const int ve  = (vs + SEG_LEN < V_DIM) ? (vs + SEG_LEN) : V_DIM;
    const float* row = w + (size_t)b * V_DIM;

    float s0 = 0.f, s1 = 0.f, s2 = 0.f, s3 = 0.f;
    int v = vs + threadIdx.x;
    for (; v + 7 * 256 < ve; v += 8 * 256) {
        float x0 = __ldg(row + v);
        float x1 = __ldg(row + v + 1 * 256);
        float x2 = __ldg(row + v + 2 * 256);
        float x3 = __ldg(row + v + 3 * 256);
        float x4 = __ldg(row + v + 4 * 256);
        float x5 = __ldg(row + v + 5 * 256);
        float x6 = __ldg(row + v + 6 * 256);
        float x7 = __ldg(row + v + 7 * 256);
        s0 += __expf(x0); s1 += __expf(x1);
        s2 += __expf(x2); s3 += __expf(x3);
        s0 += __expf(x4); s1 += __expf(x5);
        s2 += __expf(x6); s3 += __expf(x7);
    }
    for (; v < ve; v += 256) s0 += __expf(__ldg(row + v));

    {   // zero share of avg rows [N_BIN, 256)
        const float4 z = make_float4(0.f, 0.f, 0.f, 0.f);
        const int stride = gridDim.x * blockDim.x;
        for (int i = ZERO_START4 + bid * blockDim.x + threadIdx.x; i < N4_AVG; i += stride)
            avg4[i] = z;
    }

    float s = (s0 + s1) + (s2 + s3);
    #pragma unroll
    for (int o = 16; o > 0; o >>= 1)
        s += __shfl_xor_sync(0xFFFFFFFFu, s, o);

    __shared__ float ss[8];
    const int lane = threadIdx.x & 31;
    const int wid  = threadIdx.x >> 5;
    if (lane == 0) ss[wid] = s;
    __syncthreads();
    if (wid == 0) {
        s = (lane < 8) ? ss[lane] : 0.0f;
        #pragma unroll
        for (int o = 4; o > 0; o >>= 1)
            s += __shfl_xor_sync(0xFFFFFFFFu, s, o);
        if (lane == 0) g_partial[bid] = s;
    }
}

__device__ __forceinline__ float row_inv(int b) {
    return 1.0f / (__ldg(&g_partial[4 * b + 0]) + __ldg(&g_partial[4 * b + 1]) +
                   __ldg(&g_partial[4 * b + 2]) + __ldg(&g_partial[4 * b + 3]));
}

// ---------------------------------------------------------------------------
// Bin kernel (SELF-NORMALIZING -> zero dependency on stats; forks at t=0):
// one CTA per row. AtomicAdd UNNORMALIZED exp(x) into the smem bin table
// while accumulating the row sum in registers; scale by 1/s at writeout
// (scatter is linear, so this is exact).
// ---------------------------------------------------------------------------
__global__ __launch_bounds__(1024)
void bin_rows(const int*   __restrict__ idx,
              const float* __restrict__ w,
              float*       __restrict__ avg) {
    extern __shared__ float bins[];     // V_DIM floats
    const int b = blockIdx.x;
    const size_t rowoff = (size_t)b * V_DIM;

    for (int j = threadIdx.x; j < V_DIM; j += 1024) bins[j] = 0.0f;
    __syncthreads();

    float s = 0.0f;
    int i = threadIdx.x;
    for (; i + 3 * 1024 < V_DIM; i += 4 * 1024) {
        float x0 = __ldcs(w + rowoff + i);
        float x1 = __ldcs(w + rowoff + i + 1024);
        float x2 = __ldcs(w + rowoff + i + 2048);
        float x3 = __ldcs(w + rowoff + i + 3072);
        int i0 = __ldcs(idx + rowoff + i);
        int i1 = __ldcs(idx + rowoff + i + 1024);
        int i2 = __ldcs(idx + rowoff + i + 2048);
        int i3 = __ldcs(idx + rowoff + i + 3072);
        const float e0 = __expf(x0), e1 = __expf(x1);
        const float e2 = __expf(x2), e3 = __expf(x3);
        s += (e0 + e1) + (e2 + e3);
        atomicAdd(&bins[i0], e0);
        atomicAdd(&bins[i1], e1);
        atomicAdd(&bins[i2], e2);
        atomicAdd(&bins[i3], e3);
    }
    for (; i < V_DIM; i += 1024) {
        const float e = __expf(__ldcs(w + rowoff + i));
        s += e;
        atomicAdd(&bins[__ldcs(idx + rowoff + i)], e);
    }

    // block-reduce the row sum
    #pragma unroll
    for (int o = 16; o > 0; o >>= 1)
        s += __shfl_xor_sync(0xFFFFFFFFu, s, o);
    __shared__ float ssum[32];
    const int lane = threadIdx.x & 31;
    const int wid  = threadIdx.x >> 5;
    if (lane == 0) ssum[wid] = s;
    __syncthreads();
    float tot;
    {
        float t = (lane < 32) ? ssum[lane] : 0.0f;   // 32 warps
        #pragma unroll
        for (int o = 16; o > 0; o >>= 1)
            t += __shfl_xor_sync(0xFFFFFFFFu, t, o);
        tot = t;                                     // valid in warp 0
    }
    __shared__ float sinv;
    if (threadIdx.x == 0) sinv = 1.0f / tot;
    __syncthreads();
    const float inv = sinv;

    for (int j = threadIdx.x; j < V_DIM; j += 1024)
        __stcs(&avg[rowoff + j], bins[j] * inv);
}

// ---------------------------------------------------------------------------
// Tile kernel: scatter-add (rows >= N_BIN only) + transposed write (ALL rows).
// ---------------------------------------------------------------------------
__global__ __launch_bounds__(1024)
void weights_scatter_transpose(const int*   __restrict__ idx,
                               const float* __restrict__ w,
                               float*       __restrict__ avg,
                               float*       __restrict__ wT) {
    __shared__ float4 tile[32][32];

    const int vt = blockIdx.x;
    const int bt = blockIdx.y;
    const int tx = threadIdx.x;
    const int ty = threadIdx.y;

    const int b = bt * 32 + ty;
    const bool doScatter = (b >= N_BIN);
    const size_t rowoff = (size_t)b * V_DIM;
    const float inv = row_inv(b);

    const int vbase = vt * 128 + tx * 4;
    const bool full = (vbase + 3) < V_DIM;

    if (full) {
        float x[4]; int id[4];
        #pragma unroll
        for (int k = 0; k < 4; k++) x[k]  = __ldg(w + rowoff + vbase + k);
        #pragma unroll
        for (int k = 0; k < 4; k++) id[k] = __ldcs(idx + rowoff + vbase + k);

        float4 wv;
        #pragma unroll
        for (int k = 0; k < 4; k++) {
            const float e = __expf(x[k]) * inv;
            ((float*)&wv)[k] = e;
            if (doScatter) atomicAdd(&avg[rowoff + id[k]], e);  // REDG
        }
        tile[ty][tx ^ (ty >> 2)] = wv;
    } else {
        float4 wv;
        #pragma unroll
        for (int k = 0; k < 4; k++) {
            const int v = vbase + k;
            float e = 0.0f;
            if (v < V_DIM) {
                e = __expf(__ldg(w + rowoff + v)) * inv;
                if (doScatter) atomicAdd(&avg[rowoff + __ldcs(idx + rowoff + v)], e);
            }
            ((float*)&wv)[k] = e;
        }
        tile[ty][tx ^ (ty >> 2)] = wv;
    }
    __syncthreads();

    const int t = ty * 32 + tx;
    const int r = t >> 3;
    const int c = t & 7;
    const int v = vt * 128 + r;
    if (v < V_DIM) {
        const int wq  = r >> 2;
        const int sub = r & 3;
        float4 o;
        #pragma unroll
        for (int j = 0; j < 4; j++)
            ((float*)&o)[j] = ((const float*)&tile[c * 4 + j][wq ^ c])[sub];
        __stcs((float4*)&wT[(size_t)v * B_DIM + bt * 32 + c * 4], o);
    }
}

// ---------------------------------------------------------------------------
extern "C" void kernel_launch(void* const* d_in, const int* in_sizes, int n_in,
                              void* d_out, int out_size) {
    const int*   indices = (const int*)d_in[0];
    const float* w_es    = (const float*)d_in[1];

    float* avg = (float*)d_out;                           // [B, V]
    float* wT  = (float*)d_out + (size_t)B_DIM * V_DIM;   // [V, B]

    cudaStream_t s2;
    cudaEvent_t  eF, eJ;
    cudaStreamCreateWithFlags(&s2, cudaStreamNonBlocking);
    cudaEventCreateWithFlags(&eF, cudaEventDisableTiming);
    cudaEventCreateWithFlags(&eJ, cudaEventDisableTiming);
    cudaFuncSetAttribute(bin_rows, cudaFuncAttributeMaxDynamicSharedMemorySize,
                         BIN_SMEM);

    // Fork FIRST: bin_rows is self-normalizing, needs nothing from stats.
    cudaEventRecord(eF, 0);
    cudaStreamWaitEvent(s2, eF, 0);
    bin_rows<<<N_BIN, 1024, BIN_SMEM, s2>>>(indices, w_es, avg);
    cudaEventRecord(eJ, s2);

    // Main arm: stats (all rows) + zero (rows >= N_BIN), then tile.
    stats_and_zero<<<SEGS * B_DIM, 256>>>(w_es, (float4*)avg);

    dim3 grid((V_DIM + 127) / 128, B_DIM / 32);  // 393 x 8
    dim3 block(32, 32);
    weights_scatter_transpose<<<grid, block>>>(indices, w_es, avg, wT);

    // Join.
    cudaStreamWaitEvent(0, eJ, 0);
}

// round 12
// speedup vs baseline: 1.4103x; 1.4103x over previous
#include <cuda_runtime.h>
#include <math.h>

#define B_DIM 256
#define V_DIM 50257
#define SEGS  4
#define SEG_LEN 12565                 // ceil(V/4)
#define BIN_SMEM (V_DIM * 4)          // 201,028 B bin table -> 1 CTA/SM

// Partial sum-of-exp per row segment (used by transpose kernel only)
__device__ float g_partial[SEGS * B_DIM];

// ---------------------------------------------------------------------------
// Kernel A (main stream): PURE stats — per-row sum of exp, 4 CTAs/row.
// (No zeroing: bin_rows overwrites every element of avg.)
// ---------------------------------------------------------------------------
__global__ __launch_bounds__(256)
void row_stats(const float* __restrict__ w) {
    const int bid = blockIdx.x;
    const int b   = bid >> 2;
    const int seg = bid & 3;
    const int vs  = seg * SEG_LEN;
    const int ve  = (vs + SEG_LEN < V_DIM) ? (vs + SEG_LEN) : V_DIM;
    const float* row = w + (size_t)b * V_DIM;

    float s0 = 0.f, s1 = 0.f, s2 = 0.f, s3 = 0.f;
    int v = vs + threadIdx.x;
    for (; v + 7 * 256 < ve; v += 8 * 256) {
        float x0 = __ldg(row + v);
        float x1 = __ldg(row + v + 1 * 256);
        float x2 = __ldg(row + v + 2 * 256);
        float x3 = __ldg(row + v + 3 * 256);
        float x4 = __ldg(row + v + 4 * 256);
        float x5 = __ldg(row + v + 5 * 256);
        float x6 = __ldg(row + v + 6 * 256);
        float x7 = __ldg(row + v + 7 * 256);
        s0 += __expf(x0); s1 += __expf(x1);
        s2 += __expf(x2); s3 += __expf(x3);
        s0 += __expf(x4); s1 += __expf(x5);
        s2 += __expf(x6); s3 += __expf(x7);
    }
    for (; v < ve; v += 256) s0 += __expf(__ldg(row + v));

    float s = (s0 + s1) + (s2 + s3);
    #pragma unroll
    for (int o = 16; o > 0; o >>= 1)
        s += __shfl_xor_sync(0xFFFFFFFFu, s, o);

    __shared__ float ss[8];
    const int lane = threadIdx.x & 31;
    const int wid  = threadIdx.x >> 5;
    if (lane == 0) ss[wid] = s;
    __syncthreads();
    if (wid == 0) {
        s = (lane < 8) ? ss[lane] : 0.0f;
        #pragma unroll
        for (int o = 4; o > 0; o >>= 1)
            s += __shfl_xor_sync(0xFFFFFFFFu, s, o);
        if (lane == 0) g_partial[bid] = s;
    }
}

__device__ __forceinline__ float row_inv(int b) {
    return 1.0f / (__ldg(&g_partial[4 * b + 0]) + __ldg(&g_partial[4 * b + 1]) +
                   __ldg(&g_partial[4 * b + 2]) + __ldg(&g_partial[4 * b + 3]));
}

// ---------------------------------------------------------------------------
// Kernel B (side stream, forks at t=0): self-normalizing smem binning for
// ALL rows. One CTA per row: atomicAdd unnormalized exp(x) into the 201KB
// smem bin table (ATOMS - SM-local, zero LTS atomics) while accumulating
// the row sum; scale by 1/s at writeout. Fully writes avg -> no zero pass.
// ---------------------------------------------------------------------------
__global__ __launch_bounds__(1024)
void bin_rows(const int*   __restrict__ idx,
              const float* __restrict__ w,
              float*       __restrict__ avg) {
    extern __shared__ float bins[];     // V_DIM floats
    const int b = blockIdx.x;
    const size_t rowoff = (size_t)b * V_DIM;

    for (int j = threadIdx.x; j < V_DIM; j += 1024) bins[j] = 0.0f;
    __syncthreads();

    float s = 0.0f;
    int i = threadIdx.x;
    for (; i + 3 * 1024 < V_DIM; i += 4 * 1024) {
        float x0 = __ldcs(w + rowoff + i);
        float x1 = __ldcs(w + rowoff + i + 1024);
        float x2 = __ldcs(w + rowoff + i + 2048);
        float x3 = __ldcs(w + rowoff + i + 3072);
        int i0 = __ldcs(idx + rowoff + i);
        int i1 = __ldcs(idx + rowoff + i + 1024);
        int i2 = __ldcs(idx + rowoff + i + 2048);
        int i3 = __ldcs(idx + rowoff + i + 3072);
        const float e0 = __expf(x0), e1 = __expf(x1);
        const float e2 = __expf(x2), e3 = __expf(x3);
        s += (e0 + e1) + (e2 + e3);
        atomicAdd(&bins[i0], e0);
        atomicAdd(&bins[i1], e1);
        atomicAdd(&bins[i2], e2);
        atomicAdd(&bins[i3], e3);
    }
    for (; i < V_DIM; i += 1024) {
        const float e = __expf(__ldcs(w + rowoff + i));
        s += e;
        atomicAdd(&bins[__ldcs(idx + rowoff + i)], e);
    }

    // block-reduce the row sum
    #pragma unroll
    for (int o = 16; o > 0; o >>= 1)
        s += __shfl_xor_sync(0xFFFFFFFFu, s, o);
    __shared__ float ssum[32];
    const int lane = threadIdx.x & 31;
    const int wid  = threadIdx.x >> 5;
    if (lane == 0) ssum[wid] = s;
    __syncthreads();
    __shared__ float sinv;
    if (wid == 0) {
        float t = ssum[lane];               // 32 warps exactly
        #pragma unroll
        for (int o = 16; o > 0; o >>= 1)
            t += __shfl_xor_sync(0xFFFFFFFFu, t, o);
        if (lane == 0) sinv = 1.0f / t;
    }
    __syncthreads();
    const float inv = sinv;

    for (int j = threadIdx.x; j < V_DIM; j += 1024)
        __stcs(&avg[rowoff + j], bins[j] * inv);
}

// ---------------------------------------------------------------------------
// Kernel C (main stream): PURE transpose — no atomics, no idx.
// 32b x 128v tiles, XOR-swizzled float4 smem tile, conflict-free both phases.
// ---------------------------------------------------------------------------
__global__ __launch_bounds__(1024)
void transpose_only(const float* __restrict__ w,
                    float*       __restrict__ wT) {
    __shared__ float4 tile[32][32];

    const int vt = blockIdx.x;
    const int bt = blockIdx.y;
    const int tx = threadIdx.x;
    const int ty = threadIdx.y;

    const int b = bt * 32 + ty;
    const size_t rowoff = (size_t)b * V_DIM;
    const float inv = row_inv(b);

    const int vbase = vt * 128 + tx * 4;
    float4 wv;
    if (vbase + 3 < V_DIM) {
        float x[4];
        #pragma unroll
        for (int k = 0; k < 4; k++) x[k] = __ldg(w + rowoff + vbase + k);
        #pragma unroll
        for (int k = 0; k < 4; k++) ((float*)&wv)[k] = __expf(x[k]) * inv;
    } else {
        #pragma unroll
        for (int k = 0; k < 4; k++) {
            const int v = vbase + k;
            ((float*)&wv)[k] = (v < V_DIM) ? __expf(__ldg(w + rowoff + v)) * inv : 0.0f;
        }
    }
    tile[ty][tx ^ (ty >> 2)] = wv;
    __syncthreads();

    const int t = ty * 32 + tx;
    const int r = t >> 3;
    const int c = t & 7;
    const int v = vt * 128 + r;
    if (v < V_DIM) {
        const int wq  = r >> 2;
        const int sub = r & 3;
        float4 o;
        #pragma unroll
        for (int j = 0; j < 4; j++)
            ((float*)&o)[j] = ((const float*)&tile[c * 4 + j][wq ^ c])[sub];
        __stcs((float4*)&wT[(size_t)v * B_DIM + bt * 32 + c * 4], o);
    }
}

// ---------------------------------------------------------------------------
extern "C" void kernel_launch(void* const* d_in, const int* in_sizes, int n_in,
                              void* d_out, int out_size) {
    const int*   indices = (const int*)d_in[0];
    const float* w_es    = (const float*)d_in[1];

    float* avg = (float*)d_out;                           // [B, V]
    float* wT  = (float*)d_out + (size_t)B_DIM * V_DIM;   // [V, B]

    cudaStream_t s2;
    cudaEvent_t  eF, eJ;
    cudaStreamCreateWithFlags(&s2, cudaStreamNonBlocking);
    cudaEventCreateWithFlags(&eF, cudaEventDisableTiming);
    cudaEventCreateWithFlags(&eJ, cudaEventDisableTiming);
    cudaFuncSetAttribute(bin_rows, cudaFuncAttributeMaxDynamicSharedMemorySize,
                         BIN_SMEM);

    // Fork at t=0: bin_rows handles avg for ALL rows (self-normalizing).
    cudaEventRecord(eF, 0);
    cudaStreamWaitEvent(s2, eF, 0);
    bin_rows<<<B_DIM, 1024, BIN_SMEM, s2>>>(indices, w_es, avg);
    cudaEventRecord(eJ, s2);

    // Main arm (concurrent): stats -> transpose. No atomics anywhere here.
    row_stats<<<SEGS * B_DIM, 256>>>(w_es);

    dim3 tgrid((V_DIM + 127) / 128, B_DIM / 32);  // 393 x 8
    dim3 tblock(32, 32);
    transpose_only<<<tgrid, tblock>>>(w_es, wT);

    // Join.
    cudaStreamWaitEvent(0, eJ, 0);
}

// round 13
// speedup vs baseline: 1.4536x; 1.0307x over previous
#include <cuda_runtime.h>
#include <math.h>

#define B_DIM 256
#define V_DIM 50257
#define SEGS  4
#define SEG_LEN 12565                 // ceil(V/4)
#define BIN_FLOATS 50264              // V_DIM + max pad(3) + round up to /4
#define BIN_SMEM (BIN_FLOATS * 4)     // 201,056 B -> 1 CTA/SM

// Partial sum-of-exp per row segment (used by transpose kernel only)
__device__ float g_partial[SEGS * B_DIM];

// ---------------------------------------------------------------------------
// Kernel A (main stream): PURE stats — per-row sum of exp, 4 CTAs/row.
// ---------------------------------------------------------------------------
__global__ __launch_bounds__(256)
void row_stats(const float* __restrict__ w) {
    const int bid = blockIdx.x;
    const int b   = bid >> 2;
    const int seg = bid & 3;
    const int vs  = seg * SEG_LEN;
    const int ve  = (vs + SEG_LEN < V_DIM) ? (vs + SEG_LEN) : V_DIM;
    const float* row = w + (size_t)b * V_DIM;

    float s0 = 0.f, s1 = 0.f, s2 = 0.f, s3 = 0.f;
    int v = vs + threadIdx.x;
    for (; v + 7 * 256 < ve; v += 8 * 256) {
        float x0 = __ldg(row + v);
        float x1 = __ldg(row + v + 1 * 256);
        float x2 = __ldg(row + v + 2 * 256);
        float x3 = __ldg(row + v + 3 * 256);
        float x4 = __ldg(row + v + 4 * 256);
        float x5 = __ldg(row + v + 5 * 256);
        float x6 = __ldg(row + v + 6 * 256);
        float x7 = __ldg(row + v + 7 * 256);
        s0 += __expf(x0); s1 += __expf(x1);
        s2 += __expf(x2); s3 += __expf(x3);
        s0 += __expf(x4); s1 += __expf(x5);
        s2 += __expf(x6); s3 += __expf(x7);
    }
    for (; v < ve; v += 256) s0 += __expf(__ldg(row + v));

    float s = (s0 + s1) + (s2 + s3);
    #pragma unroll
    for (int o = 16; o > 0; o >>= 1)
        s += __shfl_xor_sync(0xFFFFFFFFu, s, o);

    __shared__ float ss[8];
    const int lane = threadIdx.x & 31;
    const int wid  = threadIdx.x >> 5;
    if (lane == 0) ss[wid] = s;
    __syncthreads();
    if (wid == 0) {
        s = (lane < 8) ? ss[lane] : 0.0f;
        #pragma unroll
        for (int o = 4; o > 0; o >>= 1)
            s += __shfl_xor_sync(0xFFFFFFFFu, s, o);
        if (lane == 0) g_partial[bid] = s;
    }
}

__device__ __forceinline__ float row_inv(int b) {
    return 1.0f / (__ldg(&g_partial[4 * b + 0]) + __ldg(&g_partial[4 * b + 1]) +
                   __ldg(&g_partial[4 * b + 2]) + __ldg(&g_partial[4 * b + 3]));
}

// ---------------------------------------------------------------------------
// Kernel B (side stream): self-normalizing smem binning for ALL rows,
// fully vectorized. One CTA per row.
//  - pad = rowoff&3 shifts the bin table so the writeout vector group is
//    16B-aligned on BOTH smem (LDS.128) and global (STG.128).
//  - float4/int4 input loads with scalar head/tail peel.
//  - ATOMS into bins[id + pad] (unnormalized exp); scale by 1/s at writeout.
// ---------------------------------------------------------------------------
__global__ __launch_bounds__(1024)
void bin_rows(const int*   __restrict__ idx,
              const float* __restrict__ w,
              float*       __restrict__ avg) {
    extern __shared__ float bins[];     // BIN_FLOATS floats
    const int b = blockIdx.x;
    const size_t rowoff = (size_t)b * V_DIM;
    const int pad = (int)(rowoff & 3);        // alignment phase of this row
    const int j0  = (4 - pad) & 3;            // first vec4-aligned element
    const int n4  = (V_DIM - j0) >> 2;        // full float4 groups
    const int tail0 = j0 + (n4 << 2);

    // zero the padded table (float4)
    {
        float4* b4 = (float4*)bins;
        const float4 z = make_float4(0.f, 0.f, 0.f, 0.f);
        for (int j = threadIdx.x; j < BIN_FLOATS / 4; j += 1024) b4[j] = z;
    }
    __syncthreads();

    float s = 0.0f;

    // scalar head (0..3)
    if (threadIdx.x < j0) {
        const float e = __expf(__ldcs(w + rowoff + threadIdx.x));
        s += e;
        atomicAdd(&bins[__ldcs(idx + rowoff + threadIdx.x) + pad], e);
    }

    // vector body
    const float4* w4 = (const float4*)(w + rowoff + j0);
    const int4*   i4 = (const int4*)(idx + rowoff + j0);
    for (int i = threadIdx.x; i < n4; i += 1024) {
        const float4 x  = __ldcs(w4 + i);
        const int4   id = __ldcs(i4 + i);
        const float e0 = __expf(x.x), e1 = __expf(x.y);
        const float e2 = __expf(x.z), e3 = __expf(x.w);
        s += (e0 + e1) + (e2 + e3);
        atomicAdd(&bins[id.x + pad], e0);
        atomicAdd(&bins[id.y + pad], e1);
        atomicAdd(&bins[id.z + pad], e2);
        atomicAdd(&bins[id.w + pad], e3);
    }

    // scalar tail (0..3)
    for (int j = tail0 + threadIdx.x; j < V_DIM; j += 1024) {
        const float e = __expf(__ldcs(w + rowoff + j));
        s += e;
        atomicAdd(&bins[__ldcs(idx + rowoff + j) + pad], e);
    }

    // block-reduce the row sum
    #pragma unroll
    for (int o = 16; o > 0; o >>= 1)
        s += __shfl_xor_sync(0xFFFFFFFFu, s, o);
    __shared__ float ssum[32];
    const int lane = threadIdx.x & 31;
    const int wid  = threadIdx.x >> 5;
    if (lane == 0) ssum[wid] = s;
    __syncthreads();
    __shared__ float sinv;
    if (wid == 0) {
        float t = ssum[lane];               // 32 warps exactly
        #pragma unroll
        for (int o = 16; o > 0; o >>= 1)
            t += __shfl_xor_sync(0xFFFFFFFFu, t, o);
        if (lane == 0) sinv = 1.0f / t;
    }
    __syncthreads();
    const float inv = sinv;

    // writeout: scalar head/tail, LDS.128 + STG.128 body (both 16B-aligned:
    // smem offset j+pad with j = j0+4i -> (j0+pad) % 4 == 0).
    if (threadIdx.x < j0)
        __stcs(&avg[rowoff + threadIdx.x], bins[threadIdx.x + pad] * inv);

    const float4* bv  = (const float4*)(bins + j0 + pad);
    float4*       ov  = (float4*)(avg + rowoff + j0);
    for (int i = threadIdx.x; i < n4; i += 1024) {
        float4 o = bv[i];
        o.x *= inv; o.y *= inv; o.z *= inv; o.w *= inv;
        __stcs(ov + i, o);
    }

    for (int j = tail0 + threadIdx.x; j < V_DIM; j += 1024)
        __stcs(&avg[rowoff + j], bins[j + pad] * inv);
}

// ---------------------------------------------------------------------------
// Kernel C (main stream): PURE transpose — no atomics, no idx.
// ---------------------------------------------------------------------------
__global__ __launch_bounds__(1024)
void transpose_only(const float* __restrict__ w,
                    float*       __restrict__ wT) {
    __shared__ float4 tile[32][32];

    const int vt = blockIdx.x;
    const int bt = blockIdx.y;
    const int tx = threadIdx.x;
    const int ty = threadIdx.y;

    const int b = bt * 32 + ty;
    const size_t rowoff = (size_t)b * V_DIM;
    const float inv = row_inv(b);

    const int vbase = vt * 128 + tx * 4;
    float4 wv;
    if (vbase + 3 < V_DIM) {
        float x[4];
        #pragma unroll
        for (int k = 0; k < 4; k++) x[k] = __ldg(w + rowoff + vbase + k);
        #pragma unroll
        for (int k = 0; k < 4; k++) ((float*)&wv)[k] = __expf(x[k]) * inv;
    } else {
        #pragma unroll
        for (int k = 0; k < 4; k++) {
            const int v = vbase + k;
            ((float*)&wv)[k] = (v < V_DIM) ? __expf(__ldg(w + rowoff + v)) * inv : 0.0f;
        }
    }
    tile[ty][tx ^ (ty >> 2)] = wv;
    __syncthreads();

    const int t = ty * 32 + tx;
    const int r = t >> 3;
    const int c = t & 7;
    const int v = vt * 128 + r;
    if (v < V_DIM) {
        const int wq  = r >> 2;
        const int sub = r & 3;
        float4 o;
        #pragma unroll
        for (int j = 0; j < 4; j++)
            ((float*)&o)[j] = ((const float*)&tile[c * 4 + j][wq ^ c])[sub];
        __stcs((float4*)&wT[(size_t)v * B_DIM + bt * 32 + c * 4], o);
    }
}

// ---------------------------------------------------------------------------
extern "C" void kernel_launch(void* const* d_in, const int* in_sizes, int n_in,
                              void* d_out, int out_size) {
    const int*   indices = (const int*)d_in[0];
    const float* w_es    = (const float*)d_in[1];

    float* avg = (float*)d_out;                           // [B, V]
    float* wT  = (float*)d_out + (size_t)B_DIM * V_DIM;   // [V, B]

    cudaStream_t s2;
    cudaEvent_t  eF, eJ;
    cudaStreamCreateWithFlags(&s2, cudaStreamNonBlocking);
    cudaEventCreateWithFlags(&eF, cudaEventDisableTiming);
    cudaEventCreateWithFlags(&eJ, cudaEventDisableTiming);
    cudaFuncSetAttribute(bin_rows, cudaFuncAttributeMaxDynamicSharedMemorySize,
                         BIN_SMEM);

    // Fork at t=0: bin_rows handles avg for ALL rows (self-normalizing).
    cudaEventRecord(eF, 0);
    cudaStreamWaitEvent(s2, eF, 0);
    bin_rows<<<B_DIM, 1024, BIN_SMEM, s2>>>(indices, w_es, avg);
    cudaEventRecord(eJ, s2);

    // Main arm (concurrent): stats -> transpose. No atomics anywhere here.
    row_stats<<<SEGS * B_DIM, 256>>>(w_es);

    dim3 tgrid((V_DIM + 127) / 128, B_DIM / 32);  // 393 x 8
    dim3 tblock(32, 32);
    transpose_only<<<tgrid, tblock>>>(w_es, wT);

    // Join.
    cudaStreamWaitEvent(0, eJ, 0);
}